// round 9
// baseline (speedup 1.0000x reference)
#include <cuda_runtime.h>
#include <cstdint>

// MultiHeadEMA as a chunked diagonal linear recurrence (no FFT).
// out[b,t,d] = sum_n c[d,n] * h[d,n,t] + omega[d]*x[b,t,d]
// h[t] = q*h[t-1] + x[t],  q = 1 - sigmoid(delta)*sigmoid(alpha),
// c = sigmoid(delta)*beta*gamma*sqrt(1/N)
//
// R9: state-split across lane pairs (8 states/thread, TD=256) to lift
// occupancy ceiling 43.75% -> 75% (main) / 100% (local); dot halves
// combined with shfl_xor(1). cp.async 3-stage pipeline retained.

#define cB 8
#define cL 4096
#define cD 1024
#define cN 16
#define cC 16            // chunks
#define cS (cL / cC)     // 256 steps per chunk
#define TD 256           // threads per block (2 threads per channel)
#define CHAN 128         // channels per CTA
#define ST 16            // timesteps per smem stage
#define NSTG 3           // pipeline stages
#define NSTAGE_ITERS (cS / ST)   // 16

typedef unsigned long long u64;
typedef unsigned int u32;

// scratch (static __device__ arrays: no allocations allowed)
__device__ float g_q[cD * cN];
__device__ float g_cc[cD * cN];
__device__ float g_qS[cD * cN];
__device__ float g_Le[(size_t)cB * cC * cD * cN];  // local chunk end states
__device__ float g_P[(size_t)cB * cC * cD * cN];   // prefix (init) states per chunk

__device__ __forceinline__ u64 pack2(float lo, float hi) {
    u64 r; asm("mov.b64 %0,{%1,%2};" : "=l"(r) : "f"(lo), "f"(hi)); return r;
}
__device__ __forceinline__ float2 unpack2(u64 v) {
    float2 f; asm("mov.b64 {%0,%1},%2;" : "=f"(f.x), "=f"(f.y) : "l"(v)); return f;
}
__device__ __forceinline__ u64 fma2(u64 a, u64 b, u64 c) {
    u64 d; asm("fma.rn.f32x2 %0,%1,%2,%3;" : "=l"(d) : "l"(a), "l"(b), "l"(c)); return d;
}
__device__ __forceinline__ u64 mul2(u64 a, u64 b) {
    u64 d; asm("mul.rn.f32x2 %0,%1,%2;" : "=l"(d) : "l"(a), "l"(b)); return d;
}
__device__ __forceinline__ u64 add2(u64 a, u64 b) {
    u64 d; asm("add.rn.f32x2 %0,%1,%2;" : "=l"(d) : "l"(a), "l"(b)); return d;
}
__device__ __forceinline__ void cp16(u32 saddr, const float* g) {
    asm volatile("cp.async.ca.shared.global [%0], [%1], 16;" :: "r"(saddr), "l"(g));
}
__device__ __forceinline__ void cp_commit() {
    asm volatile("cp.async.commit_group;");
}
__device__ __forceinline__ void cp_wait1() {
    asm volatile("cp.async.wait_group 1;");
}

// Issue one stage's tile (ST x CHAN floats = 8KB) via cp.async.
// TD=256 threads, each copies 8 consecutive floats (2x 16B) of the tile.
__device__ __forceinline__ void issue_stage(const float* gbase, int st,
                                            float* sbuf) {
    const float* g0 = gbase + (size_t)(st * ST) * cD;
    int base = threadIdx.x * 8;                 // 0..2040
    int row = base >> 7;                        // /CHAN
    int col = base & (CHAN - 1);
    u32 s = (u32)__cvta_generic_to_shared(sbuf + row * CHAN + col);
    const float* g = g0 + (size_t)row * cD + col;
    cp16(s, g);
    cp16(s + 16, g + 4);
}

// ---------------------------------------------------------------------------
// Kernel 0: per-(d,n) coefficients
// ---------------------------------------------------------------------------
__global__ void coeff_kernel(const float* __restrict__ delta,
                             const float* __restrict__ alpha,
                             const float* __restrict__ beta,
                             const float* __restrict__ gamma) {
    int i = blockIdx.x * blockDim.x + threadIdx.x;
    if (i >= cD * cN) return;
    float p  = 1.f / (1.f + expf(-delta[i]));
    float a  = 1.f / (1.f + expf(-alpha[i]));
    float pa = p * a;
    g_q[i]  = 1.f - pa;
    g_cc[i] = p * beta[i] * gamma[i] * 0.25f;               // scale = sqrt(1/16)
    g_qS[i] = expf((float)cS * log1pf(-pa));                // q^S, accurate near q~1
}

// ---------------------------------------------------------------------------
// Kernel A: per-chunk local end states (zero initial state)
// Each thread owns 8 of the 16 states of its channel.
// ---------------------------------------------------------------------------
__global__ void __launch_bounds__(TD, 8) local_kernel(const float* __restrict__ x) {
    __shared__ float sx[NSTG][ST][CHAN];        // 24 KB
    int ch = threadIdx.x >> 1;                  // channel within CTA
    int half = threadIdx.x & 1;                 // which 8 states
    int d = blockIdx.x * CHAN + ch;
    int c = blockIdx.y, b = blockIdx.z;
    int nb = d * cN + half * 8;                 // base into [d][n] arrays
    u64 q[4], h[4];
#pragma unroll
    for (int j = 0; j < 4; j++) {
        float2 v = *(const float2*)(g_q + nb + 2 * j);
        q[j] = pack2(v.x, v.y);
        h[j] = 0ULL;
    }
    const float* gbase = x + ((size_t)b * cL + (size_t)c * cS) * cD
                           + (size_t)blockIdx.x * CHAN;
    issue_stage(gbase, 0, &sx[0][0][0]); cp_commit();
    issue_stage(gbase, 1, &sx[1][0][0]); cp_commit();

#pragma unroll 1
    for (int s = 0; s < NSTAGE_ITERS; s++) {
        cp_wait1();
        __syncthreads();
        if (s + 2 < NSTAGE_ITERS)
            issue_stage(gbase, s + 2, &sx[(s + 2) % NSTG][0][0]);
        cp_commit();                            // uniform group count
        const float* sp = &sx[s % NSTG][0][0] + ch;
#pragma unroll
        for (int tt = 0; tt < ST; tt++) {
            float xv = sp[tt * CHAN];
            u64 a = pack2(xv, xv);
#pragma unroll
            for (int j = 0; j < 4; j++) h[j] = fma2(q[j], h[j], a);
        }
    }
    size_t pb = ((size_t)(b * cC + c) * cD) * cN + nb;
#pragma unroll
    for (int j = 0; j < 4; j++)
        *(float2*)(g_Le + pb + 2 * j) = unpack2(h[j]);
}

// ---------------------------------------------------------------------------
// Kernel B: scan across chunks: P[c] = E[c-1], E[c] = q^S * E[c-1] + Le[c]
// ---------------------------------------------------------------------------
__global__ void scan_kernel() {
    int i = blockIdx.x * blockDim.x + threadIdx.x;
    if (i >= cB * cD * cN) return;
    int dn = i % (cD * cN);
    int b  = i / (cD * cN);
    float qS = g_qS[dn];
    size_t base = (size_t)b * cC * cD * cN + dn;
    float h = 0.f;
#pragma unroll
    for (int c = 0; c < cC; c++) {
        g_P[base + (size_t)c * cD * cN] = h;
        h = fmaf(qS, h, g_Le[base + (size_t)c * cD * cN]);
    }
}

// ---------------------------------------------------------------------------
// Kernel C: full recurrence per chunk with correct initial state + residual
// ---------------------------------------------------------------------------
__global__ void __launch_bounds__(TD, 6) main_kernel(const float* __restrict__ x,
                                                     const float* __restrict__ omega,
                                                     float* __restrict__ out) {
    __shared__ float sx[NSTG][ST][CHAN];        // 24 KB
    int ch = threadIdx.x >> 1;
    int half = threadIdx.x & 1;
    int d = blockIdx.x * CHAN + ch;
    int c = blockIdx.y, b = blockIdx.z;
    int nb = d * cN + half * 8;
    u64 q[4], cc[4], h[4];
    size_t pb = ((size_t)(b * cC + c) * cD) * cN + nb;
#pragma unroll
    for (int j = 0; j < 4; j++) {
        float2 v  = *(const float2*)(g_q  + nb + 2 * j);
        float2 cv = *(const float2*)(g_cc + nb + 2 * j);
        float2 hv = *(const float2*)(g_P  + pb + 2 * j);
        q[j]  = pack2(v.x, v.y);
        cc[j] = pack2(cv.x, cv.y);
        h[j]  = pack2(hv.x, hv.y);
    }
    float w = omega[d];
    const float* gbase = x + ((size_t)b * cL + (size_t)c * cS) * cD
                           + (size_t)blockIdx.x * CHAN;
    float* op = out + ((size_t)b * cL + (size_t)c * cS) * cD + d;

    issue_stage(gbase, 0, &sx[0][0][0]); cp_commit();
    issue_stage(gbase, 1, &sx[1][0][0]); cp_commit();

#pragma unroll 1
    for (int s = 0; s < NSTAGE_ITERS; s++) {
        cp_wait1();
        __syncthreads();
        if (s + 2 < NSTAGE_ITERS)
            issue_stage(gbase, s + 2, &sx[(s + 2) % NSTG][0][0]);
        cp_commit();                            // uniform group count
        const float* sp = &sx[s % NSTG][0][0] + ch;
#pragma unroll
        for (int tt = 0; tt < ST; tt++) {
            float xv = sp[tt * CHAN];
            u64 a = pack2(xv, xv);
#pragma unroll
            for (int j = 0; j < 4; j++) h[j] = fma2(q[j], h[j], a);
            u64 s0 = mul2(cc[0], h[0]);
            u64 s1 = mul2(cc[1], h[1]);
            s0 = fma2(cc[2], h[2], s0);
            s1 = fma2(cc[3], h[3], s1);
            float2 f = unpack2(add2(s0, s1));
            float part = f.x + f.y;             // this thread's 8-state partial
            float other = __shfl_xor_sync(0xffffffffu, part, 1);
            if (half == 0)
                op[(size_t)tt * cD] = fmaf(xv, w, part + other);
        }
        op += (size_t)ST * cD;
    }
}

// ---------------------------------------------------------------------------
extern "C" void kernel_launch(void* const* d_in, const int* in_sizes, int n_in,
                              void* d_out, int out_size) {
    const float* x     = (const float*)d_in[0];
    const float* delta = (const float*)d_in[1];
    const float* alpha = (const float*)d_in[2];
    const float* beta  = (const float*)d_in[3];
    const float* gamma = (const float*)d_in[4];
    const float* omega = (const float*)d_in[5];
    float* out = (float*)d_out;

    coeff_kernel<<<(cD * cN + 255) / 256, 256>>>(delta, alpha, beta, gamma);
    dim3 grid(cD / CHAN, cC, cB);               // (8, 16, 8) = 1024 CTAs
    local_kernel<<<grid, TD>>>(x);
    scan_kernel<<<(cB * cD * cN + 255) / 256, 256>>>();
    main_kernel<<<grid, TD>>>(x, omega, out);
}

// round 10
// speedup vs baseline: 1.1390x; 1.1390x over previous
#include <cuda_runtime.h>
#include <cstdint>

// MultiHeadEMA as a chunked diagonal linear recurrence (no FFT).
// out[b,t,d] = sum_n c[d,n] * h[d,n,t] + omega[d]*x[b,t,d]
// h[t] = q*h[t-1] + x[t],  q = 1 - sigmoid(delta)*sigmoid(alpha),
// c = sigmoid(delta)*beta*gamma*sqrt(1/N)
//
// R10: single fused kernel with decoupled lookback (pass1 local states ->
// publish Le+flag -> lookback prefix -> pass2 outputs). R8 thread layout
// (TD=128, 1 chan/thread, cp.async 3-stage pipeline). All 1024 CTAs are
// co-resident (launch_bounds(128,7): 1036 slots), so spin-wait is safe.

#define cB 8
#define cL 4096
#define cD 1024
#define cN 16
#define cC 16            // chunks
#define cS (cL / cC)     // 256 steps per chunk
#define TD 128           // threads per block (1 channel per thread)
#define ST 16            // timesteps per smem stage
#define NSTG 3           // pipeline stages
#define NSTAGE_ITERS (cS / ST)   // 16
#define NDBLK (cD / TD)  // 8
#define NFLAGS (cB * cC * NDBLK) // 1024

typedef unsigned long long u64;
typedef unsigned int u32;

// scratch (static __device__ arrays: no allocations allowed)
__device__ float g_q[cD * cN];
__device__ float g_cc[cD * cN];
__device__ float g_qS[cD * cN];
__device__ float g_Le[(size_t)cB * cC * cD * cN];  // local chunk end states
__device__ volatile int g_flag[NFLAGS];            // per (b,c,dblk) publish flag

__device__ __forceinline__ u64 pack2(float lo, float hi) {
    u64 r; asm("mov.b64 %0,{%1,%2};" : "=l"(r) : "f"(lo), "f"(hi)); return r;
}
__device__ __forceinline__ float2 unpack2(u64 v) {
    float2 f; asm("mov.b64 {%0,%1},%2;" : "=f"(f.x), "=f"(f.y) : "l"(v)); return f;
}
__device__ __forceinline__ u64 fma2(u64 a, u64 b, u64 c) {
    u64 d; asm("fma.rn.f32x2 %0,%1,%2,%3;" : "=l"(d) : "l"(a), "l"(b), "l"(c)); return d;
}
__device__ __forceinline__ u64 mul2(u64 a, u64 b) {
    u64 d; asm("mul.rn.f32x2 %0,%1,%2;" : "=l"(d) : "l"(a), "l"(b)); return d;
}
__device__ __forceinline__ u64 add2(u64 a, u64 b) {
    u64 d; asm("add.rn.f32x2 %0,%1,%2;" : "=l"(d) : "l"(a), "l"(b)); return d;
}
__device__ __forceinline__ void cp16(u32 saddr, const float* g) {
    asm volatile("cp.async.ca.shared.global [%0], [%1], 16;" :: "r"(saddr), "l"(g));
}
__device__ __forceinline__ void cp_commit() {
    asm volatile("cp.async.commit_group;");
}
__device__ __forceinline__ void cp_wait1() {
    asm volatile("cp.async.wait_group 1;");
}
__device__ __forceinline__ int ld_acq(const volatile int* p) {
    int v; asm volatile("ld.acquire.gpu.b32 %0, [%1];" : "=r"(v) : "l"((const int*)p));
    return v;
}

// Issue one stage's tile (ST x TD floats = 8KB) via cp.async; 4x16B/thread.
__device__ __forceinline__ void issue_stage(const float* gbase, int st,
                                            float* sbuf) {
    const float* g0 = gbase + (size_t)(st * ST) * cD;
    int col4 = (threadIdx.x & 31) * 4;
    int r0 = threadIdx.x >> 5;
#pragma unroll
    for (int k = 0; k < 4; k++) {
        int row = r0 + 4 * k;
        u32 s = (u32)__cvta_generic_to_shared(sbuf + row * TD + col4);
        cp16(s, g0 + (size_t)row * cD + col4);
    }
}

// ---------------------------------------------------------------------------
// Kernel 0: per-(d,n) coefficients + flag clear
// ---------------------------------------------------------------------------
__global__ void coeff_kernel(const float* __restrict__ delta,
                             const float* __restrict__ alpha,
                             const float* __restrict__ beta,
                             const float* __restrict__ gamma) {
    int i = blockIdx.x * blockDim.x + threadIdx.x;
    if (i < NFLAGS) g_flag[i] = 0;
    if (i >= cD * cN) return;
    float p  = 1.f / (1.f + expf(-delta[i]));
    float a  = 1.f / (1.f + expf(-alpha[i]));
    float pa = p * a;
    g_q[i]  = 1.f - pa;
    g_cc[i] = p * beta[i] * gamma[i] * 0.25f;               // scale = sqrt(1/16)
    g_qS[i] = expf((float)cS * log1pf(-pa));                // q^S, accurate near q~1
}

// ---------------------------------------------------------------------------
// Fused kernel: pass1 local states -> publish -> lookback -> pass2 outputs
// ---------------------------------------------------------------------------
__global__ void __launch_bounds__(TD, 7) fused_kernel(const float* __restrict__ x,
                                                      const float* __restrict__ omega,
                                                      float* __restrict__ out) {
    __shared__ float sx[NSTG][ST][TD];          // 24 KB
    int d = blockIdx.x * TD + threadIdx.x;
    int c = blockIdx.y, b = blockIdx.z;
    u64 q[8], h[8];
#pragma unroll
    for (int j = 0; j < 8; j++) {
        float2 v = *(const float2*)(g_q + d * cN + 2 * j);
        q[j] = pack2(v.x, v.y);
        h[j] = 0ULL;
    }
    const float* gbase = x + ((size_t)b * cL + (size_t)c * cS) * cD
                           + (size_t)blockIdx.x * TD;

    // ---- pass 1: local end state (zero init) ----
    issue_stage(gbase, 0, &sx[0][0][0]); cp_commit();
    issue_stage(gbase, 1, &sx[1][0][0]); cp_commit();
#pragma unroll 1
    for (int s = 0; s < NSTAGE_ITERS; s++) {
        cp_wait1();
        __syncthreads();
        if (s + 2 < NSTAGE_ITERS)
            issue_stage(gbase, s + 2, &sx[(s + 2) % NSTG][0][0]);
        cp_commit();                            // uniform group count
        const float* sp = &sx[s % NSTG][0][0] + threadIdx.x;
#pragma unroll
        for (int tt = 0; tt < ST; tt++) {
            float xv = sp[tt * TD];
            u64 a = pack2(xv, xv);
#pragma unroll
            for (int j = 0; j < 8; j++) h[j] = fma2(q[j], h[j], a);
        }
    }
    // publish Le + flag
    size_t le_base = ((size_t)(b * cC + c) * cD + d) * cN;
#pragma unroll
    for (int j = 0; j < 8; j++)
        *(float2*)(g_Le + le_base + 2 * j) = unpack2(h[j]);
    __syncthreads();                            // all Le stores done; also
                                                // orders pass1 smem consumes
                                                // before pass2 issues
    int fbase = (b * cC) * NDBLK + blockIdx.x;
    if (threadIdx.x == 0) {
        __threadfence();
        g_flag[fbase + c * NDBLK] = 1;
    }

    // ---- lookback: H0 = sum_{i<c} qS^{c-1-i} * Le[i]  (redundant per CTA) ----
#pragma unroll
    for (int j = 0; j < 8; j++) h[j] = 0ULL;
    if (c > 0) {
        u64 qs[8];
#pragma unroll
        for (int j = 0; j < 8; j++) {
            float2 v = *(const float2*)(g_qS + d * cN + 2 * j);
            qs[j] = pack2(v.x, v.y);
        }
#pragma unroll 1
        for (int i = 0; i < c; i++) {
            if (threadIdx.x == 0) {
                while (ld_acq(&g_flag[fbase + i * NDBLK]) == 0)
                    __nanosleep(64);
            }
            __syncthreads();
            size_t lb = ((size_t)(b * cC + i) * cD + d) * cN;
#pragma unroll
            for (int j = 0; j < 8; j++) {
                float2 le = *(const float2*)(g_Le + lb + 2 * j);
                h[j] = fma2(qs[j], h[j], pack2(le.x, le.y));
            }
        }
    }

    // ---- pass 2: outputs with correct prefix state ----
    u64 cc[8];
#pragma unroll
    for (int j = 0; j < 8; j++) {
        float2 cv = *(const float2*)(g_cc + d * cN + 2 * j);
        cc[j] = pack2(cv.x, cv.y);
    }
    float w = omega[d];
    float* op = out + ((size_t)b * cL + (size_t)c * cS) * cD + d;

    issue_stage(gbase, 0, &sx[0][0][0]); cp_commit();
    issue_stage(gbase, 1, &sx[1][0][0]); cp_commit();
#pragma unroll 1
    for (int s = 0; s < NSTAGE_ITERS; s++) {
        cp_wait1();
        __syncthreads();
        if (s + 2 < NSTAGE_ITERS)
            issue_stage(gbase, s + 2, &sx[(s + 2) % NSTG][0][0]);
        cp_commit();                            // uniform group count
        const float* sp = &sx[s % NSTG][0][0] + threadIdx.x;
#pragma unroll
        for (int tt = 0; tt < ST; tt++) {
            float xv = sp[tt * TD];
            u64 a = pack2(xv, xv);
#pragma unroll
            for (int j = 0; j < 8; j++) h[j] = fma2(q[j], h[j], a);
            u64 s0 = mul2(cc[0], h[0]);
            u64 s1 = mul2(cc[1], h[1]);
            s0 = fma2(cc[2], h[2], s0);  s1 = fma2(cc[3], h[3], s1);
            s0 = fma2(cc[4], h[4], s0);  s1 = fma2(cc[5], h[5], s1);
            s0 = fma2(cc[6], h[6], s0);  s1 = fma2(cc[7], h[7], s1);
            float2 f = unpack2(add2(s0, s1));
            op[(size_t)tt * cD] = fmaf(xv, w, f.x + f.y);
        }
        op += (size_t)ST * cD;
    }
}

// ---------------------------------------------------------------------------
extern "C" void kernel_launch(void* const* d_in, const int* in_sizes, int n_in,
                              void* d_out, int out_size) {
    const float* x     = (const float*)d_in[0];
    const float* delta = (const float*)d_in[1];
    const float* alpha = (const float*)d_in[2];
    const float* beta  = (const float*)d_in[3];
    const float* gamma = (const float*)d_in[4];
    const float* omega = (const float*)d_in[5];
    float* out = (float*)d_out;

    coeff_kernel<<<(cD * cN + 255) / 256, 256>>>(delta, alpha, beta, gamma);
    dim3 grid(NDBLK, cC, cB);                   // (8, 16, 8) = 1024 CTAs
    fused_kernel<<<grid, TD>>>(x, omega, out);
}